// round 2
// baseline (speedup 1.0000x reference)
#include <cuda_runtime.h>

#define NN 100000
#define NE 1200000
#define NB ((NN + 255) / 256)        // 391 scan blocks
#define NT64 ((NN + 63) / 64)        // 1563 GEMM tiles (64 rows)

typedef unsigned long long u64;

// ---------------- scratch (static device memory) ---------------------------
__device__ int   g_deg[NN];
__device__ int   g_cnt[NN];
__device__ int   g_fill[NN];
__device__ int   g_rp[NN + 1];
__device__ int   g_bsum[NB + 1];
__device__ int   g_col[NE];
__device__ float g_w[NE];
__device__ float g_dinv[NN];
__device__ float g_T1[NN * 64];
__device__ float g_T2[NN * 64];
__device__ float g_T3[NN * 64];
__device__ float g_Ha[NN * 64];
__device__ float g_Hb[NN * 64];
__device__ float g_A[NN * 32];
__device__ float g_B[NN * 32];

// ---------------- f32x2 helpers --------------------------------------------
__device__ __forceinline__ void ffma2(u64& d, u64 a, u64 b) {
    asm("fma.rn.f32x2 %0, %1, %2, %0;" : "+l"(d) : "l"(a), "l"(b));
}
__device__ __forceinline__ u64 dup2(float a) {
    u64 r; asm("mov.b64 %0, {%1, %1};" : "=l"(r) : "f"(a)); return r;
}
__device__ __forceinline__ float2 unp2(u64 v) {
    float2 f; asm("mov.b64 {%0, %1}, %2;" : "=f"(f.x), "=f"(f.y) : "l"(v)); return f;
}

// ---------------- setup kernels --------------------------------------------
__global__ void k_zero3() {
    int i = blockIdx.x * blockDim.x + threadIdx.x;
    if (i < NN) { g_deg[i] = 0; g_cnt[i] = 0; g_fill[i] = 0; }
}

__global__ void k_degcnt(const int* __restrict__ src, const int* __restrict__ dst) {
    int i = blockIdx.x * blockDim.x + threadIdx.x;
    if (i < NE) {
        atomicAdd(&g_deg[src[i]], 1);
        atomicAdd(&g_cnt[dst[i]], 1);
    }
}

__global__ void k_dinv() {
    int i = blockIdx.x * blockDim.x + threadIdx.x;
    if (i < NN) {
        int d = g_deg[i];
        g_dinv[i] = (d > 0) ? rsqrtf((float)d) : 0.0f;
    }
}

// phase 1: per-block sums of g_cnt
__global__ void k_scan1() {
    __shared__ int s[8];
    const int t = threadIdx.x;
    int i = blockIdx.x * 256 + t;
    int v = (i < NN) ? g_cnt[i] : 0;
    #pragma unroll
    for (int d = 16; d; d >>= 1) v += __shfl_down_sync(0xffffffffu, v, d);
    if ((t & 31) == 0) s[t >> 5] = v;
    __syncthreads();
    if (t < 8) {
        int x = s[t];
        #pragma unroll
        for (int d = 4; d; d >>= 1) x += __shfl_down_sync(0xffu, x, d);
        if (t == 0) g_bsum[blockIdx.x] = x;
    }
}

// phase 2: exclusive scan of NB block sums (1 block, 512 threads)
__global__ void k_scan2() {
    __shared__ int wsum[16];
    const int t = threadIdx.x;
    int v = (t < NB) ? g_bsum[t] : 0;
    int xv = v;
    #pragma unroll
    for (int d = 1; d < 32; d <<= 1) {
        int y = __shfl_up_sync(0xffffffffu, xv, d);
        if ((t & 31) >= d) xv += y;
    }
    if ((t & 31) == 31) wsum[t >> 5] = xv;
    __syncthreads();
    if (t < 16) {
        int wv = wsum[t];
        int yv = wv;
        #pragma unroll
        for (int d = 1; d < 16; d <<= 1) {
            int z = __shfl_up_sync(0xffffu, yv, d);
            if (t >= d) yv += z;
        }
        wsum[t] = yv - wv;
    }
    __syncthreads();
    int incl = xv + wsum[t >> 5];
    int excl = incl - v;
    if (t < NB) g_bsum[t] = excl;
    if (t == NB - 1) g_rp[NN] = incl;
}

// phase 3: per-block exclusive scan + block offset
__global__ void k_scan3() {
    __shared__ int wsum[8];
    const int t = threadIdx.x;
    int i = blockIdx.x * 256 + t;
    int v = (i < NN) ? g_cnt[i] : 0;
    int xv = v;
    #pragma unroll
    for (int d = 1; d < 32; d <<= 1) {
        int y = __shfl_up_sync(0xffffffffu, xv, d);
        if ((t & 31) >= d) xv += y;
    }
    if ((t & 31) == 31) wsum[t >> 5] = xv;
    __syncthreads();
    if (t < 8) {
        int wv = wsum[t];
        int yv = wv;
        #pragma unroll
        for (int d = 1; d < 8; d <<= 1) {
            int z = __shfl_up_sync(0xffu, yv, d);
            if (t >= d) yv += z;
        }
        wsum[t] = yv - wv;
    }
    __syncthreads();
    if (i < NN) g_rp[i] = xv - v + wsum[t >> 5] + g_bsum[blockIdx.x];
}

__global__ void k_scatter(const int* __restrict__ src, const int* __restrict__ dst) {
    int i = blockIdx.x * blockDim.x + threadIdx.x;
    if (i < NE) {
        int s = src[i], d = dst[i];
        int pos = g_rp[d] + atomicAdd(&g_fill[d], 1);
        g_col[pos] = s;
        g_w[pos] = -g_dinv[s] * g_dinv[d];
    }
}

// ---------------- sparse matvec: out = alpha*(L z) + beta*sub (width 64) ---
__global__ void k_lmv64(const float* __restrict__ z, const float* __restrict__ sub,
                        float* __restrict__ outp, float alpha, float beta) {
    int gt = blockIdx.x * blockDim.x + threadIdx.x;
    int node = gt >> 5;
    if (node >= NN) return;
    int lane = gt & 31;
    int beg = g_rp[node], end = g_rp[node + 1];
    const float2* z2 = (const float2*)z;
    float2 a0 = make_float2(0.f, 0.f), a1 = a0, a2 = a0, a3 = a0;
    int e = beg;
    for (; e + 4 <= end; e += 4) {
        int   c0 = g_col[e],   c1 = g_col[e+1],   c2 = g_col[e+2],   c3 = g_col[e+3];
        float w0 = g_w[e],     w1 = g_w[e+1],     w2 = g_w[e+2],     w3 = g_w[e+3];
        float2 v0 = z2[c0 * 32 + lane];
        float2 v1 = z2[c1 * 32 + lane];
        float2 v2 = z2[c2 * 32 + lane];
        float2 v3 = z2[c3 * 32 + lane];
        a0.x += w0 * v0.x; a0.y += w0 * v0.y;
        a1.x += w1 * v1.x; a1.y += w1 * v1.y;
        a2.x += w2 * v2.x; a2.y += w2 * v2.y;
        a3.x += w3 * v3.x; a3.y += w3 * v3.y;
    }
    for (; e < end; e++) {
        int c = g_col[e]; float we = g_w[e];
        float2 v = z2[c * 32 + lane];
        a0.x += we * v.x; a0.y += we * v.y;
    }
    float2 acc = make_float2(a0.x + a1.x + a2.x + a3.x, a0.y + a1.y + a2.y + a3.y);
    float2 r;
    if (sub) {
        float2 sv = ((const float2*)sub)[node * 32 + lane];
        r.x = alpha * acc.x + beta * sv.x;
        r.y = alpha * acc.y + beta * sv.y;
    } else {
        r.x = alpha * acc.x;
        r.y = alpha * acc.y;
    }
    ((float2*)outp)[node * 32 + lane] = r;
}

// ---------------- fused layer GEMM (f32x2) ---------------------------------
// out = relu([T0|T1|T2|T3] @ Wk + bk) + T0 @ Ws + bs
// tile 64 rows x 64 cols; thread: 2 rows x 8 cols (f32x2 packed over col pairs)
#define INS_STRIDE 260
#define SMEM_LAYER ((16384 + 4096 + 64 + 64 + 64 * INS_STRIDE) * 4)
__global__ void __launch_bounds__(256, 1) k_layer(
        const float* __restrict__ T0,
        const float* __restrict__ Wk, const float* __restrict__ bk,
        const float* __restrict__ Ws, const float* __restrict__ bs,
        float* __restrict__ outp) {
    extern __shared__ float sm[];
    float* Wk_s = sm;              // 16384
    float* Ws_s = sm + 16384;      // 4096
    float* bk_s = sm + 20480;      // 64
    float* bs_s = sm + 20544;      // 64
    float* ins  = sm + 20608;      // 64 x 260
    const int t = threadIdx.x;     // 256 threads

    for (int j = t; j < 4096; j += 256) ((float4*)Wk_s)[j] = ((const float4*)Wk)[j];
    for (int j = t; j < 1024; j += 256) ((float4*)Ws_s)[j] = ((const float4*)Ws)[j];
    if (t < 64) { bk_s[t] = bk[t]; bs_s[t] = bs[t]; }

    const int cg = (t & 7) * 8;    // 8 output cols
    const int r0 = (t >> 3) * 2;   // 2 rows

    for (int tile = blockIdx.x; tile < NT64; tile += gridDim.x) {
        const int rowbase = tile * 64;
        __syncthreads();
        {
            const float4* s0 = (const float4*)T0;
            const float4* s1 = (const float4*)g_T1;
            const float4* s2 = (const float4*)g_T2;
            const float4* s3 = (const float4*)g_T3;
            #pragma unroll
            for (int j = 0; j < 16; j++) {
                int idx = t + j * 256;            // 4096 float4 slots
                int r = idx >> 6, f4 = idx & 63;
                int row = rowbase + r; if (row >= NN) row = NN - 1;
                int seg = f4 >> 4, cf = f4 & 15;
                int gidx = row * 16 + cf;
                float4 v;
                if (seg == 0) v = s0[gidx];
                else if (seg == 1) v = s1[gidx];
                else if (seg == 2) v = s2[gidx];
                else v = s3[gidx];
                *(float4*)&ins[r * INS_STRIDE + f4 * 4] = v;
            }
        }
        __syncthreads();

        const float* in0 = &ins[r0 * INS_STRIDE];
        const float* in1 = in0 + INS_STRIDE;
        u64 k00 = 0, k01 = 0, k02 = 0, k03 = 0;   // row r0, col pairs
        u64 k10 = 0, k11 = 0, k12 = 0, k13 = 0;   // row r0+1
        #pragma unroll 4
        for (int kk = 0; kk < 256; kk++) {
            const u64* wp = (const u64*)&Wk_s[kk * 64 + cg];
            u64 w0 = wp[0], w1 = wp[1], w2 = wp[2], w3 = wp[3];
            u64 ad0 = dup2(in0[kk]);
            u64 ad1 = dup2(in1[kk]);
            ffma2(k00, ad0, w0); ffma2(k01, ad0, w1);
            ffma2(k02, ad0, w2); ffma2(k03, ad0, w3);
            ffma2(k10, ad1, w0); ffma2(k11, ad1, w1);
            ffma2(k12, ad1, w2); ffma2(k13, ad1, w3);
        }
        u64 s00 = 0, s01 = 0, s02 = 0, s03 = 0;
        u64 s10 = 0, s11 = 0, s12 = 0, s13 = 0;
        #pragma unroll 4
        for (int kk = 0; kk < 64; kk++) {
            const u64* wp = (const u64*)&Ws_s[kk * 64 + cg];
            u64 w0 = wp[0], w1 = wp[1], w2 = wp[2], w3 = wp[3];
            u64 ad0 = dup2(in0[kk]);
            u64 ad1 = dup2(in1[kk]);
            ffma2(s00, ad0, w0); ffma2(s01, ad0, w1);
            ffma2(s02, ad0, w2); ffma2(s03, ad0, w3);
            ffma2(s10, ad1, w0); ffma2(s11, ad1, w1);
            ffma2(s12, ad1, w2); ffma2(s13, ad1, w3);
        }

        int row = rowbase + r0;
        u64 kA[8] = {k00, k01, k02, k03, k10, k11, k12, k13};
        u64 sA[8] = {s00, s01, s02, s03, s10, s11, s12, s13};
        #pragma unroll
        for (int rr = 0; rr < 2; rr++) {
            if (row + rr < NN) {
                float o[8];
                #pragma unroll
                for (int j = 0; j < 4; j++) {
                    float2 kv = unp2(kA[rr * 4 + j]);
                    float2 sv = unp2(sA[rr * 4 + j]);
                    int c = cg + j * 2;
                    o[j*2+0] = fmaxf(kv.x + bk_s[c+0], 0.f) + sv.x + bs_s[c+0];
                    o[j*2+1] = fmaxf(kv.y + bk_s[c+1], 0.f) + sv.y + bs_s[c+1];
                }
                *(float4*)&outp[(row + rr) * 64 + cg]     = *(float4*)&o[0];
                *(float4*)&outp[(row + rr) * 64 + cg + 4] = *(float4*)&o[4];
            }
        }
    }
}

// ---------------- mix head GEMM (f32x2): A = hc@W1, B = hc@W0 + b ----------
#define MIX_STRIDE 132
#define SMEM_MIX ((8192 + 32 + 64 * MIX_STRIDE) * 4)
__global__ void __launch_bounds__(256, 1) k_mixgemm(
        const float* __restrict__ H, const float* __restrict__ x,
        const float* __restrict__ mw, const float* __restrict__ mb) {
    extern __shared__ float sm[];
    float* Wm_s = sm;            // 8192: [128][64], cols 0..31 = W1, 32..63 = W0
    float* mb_s = sm + 8192;     // 32
    float* ins  = sm + 8224;     // 64 x 132
    const int t = threadIdx.x;

    for (int j = t; j < 8192; j += 256) {
        int f = j >> 6, col = j & 63;
        Wm_s[j] = (col < 32) ? mw[128 * 32 + f * 32 + col] : mw[f * 32 + (col - 32)];
    }
    if (t < 32) mb_s[t] = mb[t];

    const int cg = (t & 7) * 8;
    const int r0 = (t >> 3) * 2;

    for (int tile = blockIdx.x; tile < NT64; tile += gridDim.x) {
        const int rowbase = tile * 64;
        __syncthreads();
        {
            const float4* sH = (const float4*)H;
            const float4* sx = (const float4*)x;
            #pragma unroll
            for (int j = 0; j < 8; j++) {
                int idx = t + j * 256;            // 2048 float4 slots
                int r = idx >> 5, f4 = idx & 31;
                int row = rowbase + r; if (row >= NN) row = NN - 1;
                int cf = f4 & 15;
                int gidx = row * 16 + cf;
                float4 v = (f4 < 16) ? sH[gidx] : sx[gidx];
                *(float4*)&ins[r * MIX_STRIDE + f4 * 4] = v;
            }
        }
        __syncthreads();

        const float* in0 = &ins[r0 * MIX_STRIDE];
        const float* in1 = in0 + MIX_STRIDE;
        u64 k00 = 0, k01 = 0, k02 = 0, k03 = 0;
        u64 k10 = 0, k11 = 0, k12 = 0, k13 = 0;
        #pragma unroll 4
        for (int kk = 0; kk < 128; kk++) {
            const u64* wp = (const u64*)&Wm_s[kk * 64 + cg];
            u64 w0 = wp[0], w1 = wp[1], w2 = wp[2], w3 = wp[3];
            u64 ad0 = dup2(in0[kk]);
            u64 ad1 = dup2(in1[kk]);
            ffma2(k00, ad0, w0); ffma2(k01, ad0, w1);
            ffma2(k02, ad0, w2); ffma2(k03, ad0, w3);
            ffma2(k10, ad1, w0); ffma2(k11, ad1, w1);
            ffma2(k12, ad1, w2); ffma2(k13, ad1, w3);
        }

        int row = rowbase + r0;
        u64 kA[8] = {k00, k01, k02, k03, k10, k11, k12, k13};
        #pragma unroll
        for (int rr = 0; rr < 2; rr++) {
            if (row + rr < NN) {
                float o[8];
                #pragma unroll
                for (int j = 0; j < 4; j++) {
                    float2 kv = unp2(kA[rr * 4 + j]);
                    o[j*2+0] = kv.x;
                    o[j*2+1] = kv.y;
                }
                if (cg < 32) {
                    *(float4*)&g_A[(row + rr) * 32 + cg]     = *(float4*)&o[0];
                    *(float4*)&g_A[(row + rr) * 32 + cg + 4] = *(float4*)&o[4];
                } else {
                    int cb = cg - 32;
                    #pragma unroll
                    for (int j = 0; j < 8; j++) o[j] += mb_s[cb + j];
                    *(float4*)&g_B[(row + rr) * 32 + cb]     = *(float4*)&o[0];
                    *(float4*)&g_B[(row + rr) * 32 + cb + 4] = *(float4*)&o[4];
                }
            }
        }
    }
}

// ---------------- final: out = B + L(A) (width 32) -------------------------
__global__ void k_mixlmv(float* __restrict__ outp) {
    int gt = blockIdx.x * blockDim.x + threadIdx.x;
    int node = gt >> 5;
    if (node >= NN) return;
    int lane = gt & 31;
    int beg = g_rp[node], end = g_rp[node + 1];
    float a0 = 0.f, a1 = 0.f, a2 = 0.f, a3 = 0.f;
    int e = beg;
    for (; e + 4 <= end; e += 4) {
        int   c0 = g_col[e],   c1 = g_col[e+1],   c2 = g_col[e+2],   c3 = g_col[e+3];
        float w0 = g_w[e],     w1 = g_w[e+1],     w2 = g_w[e+2],     w3 = g_w[e+3];
        a0 += w0 * g_A[c0 * 32 + lane];
        a1 += w1 * g_A[c1 * 32 + lane];
        a2 += w2 * g_A[c2 * 32 + lane];
        a3 += w3 * g_A[c3 * 32 + lane];
    }
    for (; e < end; e++) a0 += g_w[e] * g_A[g_col[e] * 32 + lane];
    outp[node * 32 + lane] = g_B[node * 32 + lane] + (a0 + a1) + (a2 + a3);
}

// ---------------- launch ---------------------------------------------------
extern "C" void kernel_launch(void* const* d_in, const int* in_sizes, int n_in,
                              void* d_out, int out_size) {
    const float* x  = (const float*)d_in[0];
    const int*   ei = (const int*)d_in[1];
    const float* kw = (const float*)d_in[2];   // [3][4][64][64]
    const float* kb = (const float*)d_in[3];   // [3][64]
    const float* sw = (const float*)d_in[4];   // [3][64][64]
    const float* sb = (const float*)d_in[5];   // [3][64]
    const float* mw = (const float*)d_in[6];   // [2][128][32]
    const float* mb = (const float*)d_in[7];   // [32]
    float* outp = (float*)d_out;
    const int* src = ei;
    const int* dst = ei + NE;

    float *T1, *T2, *T3, *Ha, *Hb;
    cudaGetSymbolAddress((void**)&T1, g_T1);
    cudaGetSymbolAddress((void**)&T2, g_T2);
    cudaGetSymbolAddress((void**)&T3, g_T3);
    cudaGetSymbolAddress((void**)&Ha, g_Ha);
    cudaGetSymbolAddress((void**)&Hb, g_Hb);

    cudaFuncSetAttribute(k_layer, cudaFuncAttributeMaxDynamicSharedMemorySize, SMEM_LAYER);
    cudaFuncSetAttribute(k_mixgemm, cudaFuncAttributeMaxDynamicSharedMemorySize, SMEM_MIX);

    const int gE = (NE + 255) / 256;       // 4688
    const int gN = NB;                     // 391
    const int gW = (NN * 32 + 255) / 256;  // 12500 (warp per node)
    const int gG = 148;                    // persistent GEMM grid (1 block/SM)

    // graph setup: degrees, dinv, CSR by dst
    k_zero3<<<gN, 256>>>();
    k_degcnt<<<gE, 256>>>(src, dst);
    k_dinv<<<gN, 256>>>();
    k_scan1<<<gN, 256>>>();
    k_scan2<<<1, 512>>>();
    k_scan3<<<gN, 256>>>();
    k_scatter<<<gE, 256>>>(src, dst);

    // layer 0: input = x, output = Hb
    k_lmv64<<<gW, 256>>>(x, nullptr, T1, 1.f, 0.f);
    k_lmv64<<<gW, 256>>>(T1, x, T2, 2.f, -1.f);
    k_lmv64<<<gW, 256>>>(T2, T1, T3, 2.f, -1.f);
    k_layer<<<gG, 256, SMEM_LAYER>>>(x, kw, kb, sw, sb, Hb);

    // layer 1: Hb -> Ha
    k_lmv64<<<gW, 256>>>(Hb, nullptr, T1, 1.f, 0.f);
    k_lmv64<<<gW, 256>>>(T1, Hb, T2, 2.f, -1.f);
    k_lmv64<<<gW, 256>>>(T2, T1, T3, 2.f, -1.f);
    k_layer<<<gG, 256, SMEM_LAYER>>>(Hb, kw + 4 * 64 * 64, kb + 64, sw + 64 * 64, sb + 64, Ha);

    // layer 2: Ha -> Hb
    k_lmv64<<<gW, 256>>>(Ha, nullptr, T1, 1.f, 0.f);
    k_lmv64<<<gW, 256>>>(T1, Ha, T2, 2.f, -1.f);
    k_lmv64<<<gW, 256>>>(T2, T1, T3, 2.f, -1.f);
    k_layer<<<gG, 256, SMEM_LAYER>>>(Ha, kw + 8 * 64 * 64, kb + 128, sw + 2 * 64 * 64, sb + 128, Hb);

    // mix head: A = [Hb|x]@W1, B = [Hb|x]@W0 + b; out = B + L(A)
    k_mixgemm<<<gG, 256, SMEM_MIX>>>(Hb, x, mw, mb);
    k_mixlmv<<<gW, 256>>>(outp);
}

// round 4
// speedup vs baseline: 1.3563x; 1.3563x over previous
#include <cuda_runtime.h>

#define NN 100000
#define NE 1200000
#define NB ((NN + 255) / 256)        // 391 scan blocks
#define NT64 ((NN + 63) / 64)        // 1563 GEMM tiles (64 rows)

// ---------------- scratch (static device memory) ---------------------------
__device__ int    g_deg[NN];
__device__ int    g_cnt[NN];
__device__ int    g_fill[NN];
__device__ int    g_rp[NN + 1];
__device__ int    g_bsum[NB + 1];
__device__ float2 g_wc[NE];          // packed (weight, col-as-bits)
__device__ float  g_dinv[NN];
__device__ float  g_T1[NN * 64];
__device__ float  g_T2[NN * 64];
__device__ float  g_T3[NN * 64];
__device__ float  g_Ha[NN * 64];
__device__ float  g_Hb[NN * 64];
__device__ float  g_A[NN * 32];
__device__ float  g_B[NN * 32];

// ---------------- setup kernels --------------------------------------------
__global__ void k_zero3() {
    int i = blockIdx.x * blockDim.x + threadIdx.x;
    if (i < NN) { g_deg[i] = 0; g_cnt[i] = 0; g_fill[i] = 0; }
}

__global__ void k_degcnt(const int* __restrict__ src, const int* __restrict__ dst) {
    int i = blockIdx.x * blockDim.x + threadIdx.x;
    if (i < NE) {
        atomicAdd(&g_deg[src[i]], 1);
        atomicAdd(&g_cnt[dst[i]], 1);
    }
}

__global__ void k_dinv() {
    int i = blockIdx.x * blockDim.x + threadIdx.x;
    if (i < NN) {
        int d = g_deg[i];
        g_dinv[i] = (d > 0) ? rsqrtf((float)d) : 0.0f;
    }
}

// phase 1: per-block sums of g_cnt
__global__ void k_scan1() {
    __shared__ int s[8];
    const int t = threadIdx.x;
    int i = blockIdx.x * 256 + t;
    int v = (i < NN) ? g_cnt[i] : 0;
    #pragma unroll
    for (int d = 16; d; d >>= 1) v += __shfl_down_sync(0xffffffffu, v, d);
    if ((t & 31) == 0) s[t >> 5] = v;
    __syncthreads();
    if (t < 8) {
        int x = s[t];
        #pragma unroll
        for (int d = 4; d; d >>= 1) x += __shfl_down_sync(0xffu, x, d);
        if (t == 0) g_bsum[blockIdx.x] = x;
    }
}

// phase 2: exclusive scan of NB block sums (1 block, 512 threads)
__global__ void k_scan2() {
    __shared__ int wsum[16];
    const int t = threadIdx.x;
    int v = (t < NB) ? g_bsum[t] : 0;
    int xv = v;
    #pragma unroll
    for (int d = 1; d < 32; d <<= 1) {
        int y = __shfl_up_sync(0xffffffffu, xv, d);
        if ((t & 31) >= d) xv += y;
    }
    if ((t & 31) == 31) wsum[t >> 5] = xv;
    __syncthreads();
    if (t < 16) {
        int wv = wsum[t];
        int yv = wv;
        #pragma unroll
        for (int d = 1; d < 16; d <<= 1) {
            int z = __shfl_up_sync(0xffffu, yv, d);
            if (t >= d) yv += z;
        }
        wsum[t] = yv - wv;
    }
    __syncthreads();
    int incl = xv + wsum[t >> 5];
    int excl = incl - v;
    if (t < NB) g_bsum[t] = excl;
    if (t == NB - 1) g_rp[NN] = incl;
}

// phase 3: per-block exclusive scan + block offset
__global__ void k_scan3() {
    __shared__ int wsum[8];
    const int t = threadIdx.x;
    int i = blockIdx.x * 256 + t;
    int v = (i < NN) ? g_cnt[i] : 0;
    int xv = v;
    #pragma unroll
    for (int d = 1; d < 32; d <<= 1) {
        int y = __shfl_up_sync(0xffffffffu, xv, d);
        if ((t & 31) >= d) xv += y;
    }
    if ((t & 31) == 31) wsum[t >> 5] = xv;
    __syncthreads();
    if (t < 8) {
        int wv = wsum[t];
        int yv = wv;
        #pragma unroll
        for (int d = 1; d < 8; d <<= 1) {
            int z = __shfl_up_sync(0xffu, yv, d);
            if (t >= d) yv += z;
        }
        wsum[t] = yv - wv;
    }
    __syncthreads();
    if (i < NN) g_rp[i] = xv - v + wsum[t >> 5] + g_bsum[blockIdx.x];
}

__global__ void k_scatter(const int* __restrict__ src, const int* __restrict__ dst) {
    int i = blockIdx.x * blockDim.x + threadIdx.x;
    if (i < NE) {
        int s = src[i], d = dst[i];
        int pos = g_rp[d] + atomicAdd(&g_fill[d], 1);
        g_wc[pos] = make_float2(-g_dinv[s] * g_dinv[d], __int_as_float(s));
    }
}

// ---------------- sparse matvec: out = alpha*(L z) + beta*sub (width 64) ---
__global__ void k_lmv64(const float* __restrict__ z, const float* __restrict__ sub,
                        float* __restrict__ outp, float alpha, float beta) {
    int gt = blockIdx.x * blockDim.x + threadIdx.x;
    int node = gt >> 5;
    if (node >= NN) return;
    int lane = gt & 31;
    int beg = g_rp[node], end = g_rp[node + 1];
    const float2* z2 = (const float2*)z;
    float2 a0 = make_float2(0.f, 0.f), a1 = a0, a2 = a0, a3 = a0;
    int e = beg;
    for (; e + 4 <= end; e += 4) {
        float2 p0 = g_wc[e], p1 = g_wc[e+1], p2 = g_wc[e+2], p3 = g_wc[e+3];
        float2 v0 = z2[__float_as_int(p0.y) * 32 + lane];
        float2 v1 = z2[__float_as_int(p1.y) * 32 + lane];
        float2 v2 = z2[__float_as_int(p2.y) * 32 + lane];
        float2 v3 = z2[__float_as_int(p3.y) * 32 + lane];
        a0.x += p0.x * v0.x; a0.y += p0.x * v0.y;
        a1.x += p1.x * v1.x; a1.y += p1.x * v1.y;
        a2.x += p2.x * v2.x; a2.y += p2.x * v2.y;
        a3.x += p3.x * v3.x; a3.y += p3.x * v3.y;
    }
    for (; e < end; e++) {
        float2 p = g_wc[e];
        float2 v = z2[__float_as_int(p.y) * 32 + lane];
        a0.x += p.x * v.x; a0.y += p.x * v.y;
    }
    float2 acc = make_float2(a0.x + a1.x + a2.x + a3.x, a0.y + a1.y + a2.y + a3.y);
    float2 r;
    if (sub) {
        float2 sv = ((const float2*)sub)[node * 32 + lane];
        r.x = alpha * acc.x + beta * sv.x;
        r.y = alpha * acc.y + beta * sv.y;
    } else {
        r.x = alpha * acc.x;
        r.y = alpha * acc.y;
    }
    ((float2*)outp)[node * 32 + lane] = r;
}

// ---------------- fused layer GEMM (scalar FFMA, 4x4 blocking) -------------
// out = relu([T0|T1|T2|T3] @ Wk + bk) + T0 @ Ws + bs
// tile 64 rows x 64 cols, 256 threads, 4 rows x 4 cols per thread
#define INS_STRIDE 260
#define SMEM_LAYER ((16384 + 4096 + 64 + 64 + 64 * INS_STRIDE) * 4)
__global__ void __launch_bounds__(256, 1) k_layer(
        const float* __restrict__ T0,
        const float* __restrict__ Wk, const float* __restrict__ bk,
        const float* __restrict__ Ws, const float* __restrict__ bs,
        float* __restrict__ outp) {
    extern __shared__ float sm[];
    float* Wk_s = sm;              // 16384 [256][64]
    float* Ws_s = sm + 16384;      // 4096  [64][64]
    float* bk_s = sm + 20480;      // 64
    float* bs_s = sm + 20544;      // 64
    float* ins  = sm + 20608;      // 64 x 260
    const int t = threadIdx.x;     // 256 threads

    for (int j = t; j < 4096; j += 256) ((float4*)Wk_s)[j] = ((const float4*)Wk)[j];
    for (int j = t; j < 1024; j += 256) ((float4*)Ws_s)[j] = ((const float4*)Ws)[j];
    if (t < 64) { bk_s[t] = bk[t]; bs_s[t] = bs[t]; }

    const int cg4 = (t & 15) * 4;   // 4 output cols
    const int rg4 = (t >> 4) * 4;   // 4 rows

    for (int tile = blockIdx.x; tile < NT64; tile += gridDim.x) {
        const int rowbase = tile * 64;
        __syncthreads();
        {
            const float4* s0 = (const float4*)T0;
            const float4* s1 = (const float4*)g_T1;
            const float4* s2 = (const float4*)g_T2;
            const float4* s3 = (const float4*)g_T3;
            #pragma unroll
            for (int j = 0; j < 16; j++) {
                int idx = t + j * 256;            // 4096 float4 slots
                int r = idx >> 6, f4 = idx & 63;
                int row = min(rowbase + r, NN - 1);
                int seg = f4 >> 4, cf = f4 & 15;
                int gidx = row * 16 + cf;
                float4 v;
                if (seg == 0) v = s0[gidx];
                else if (seg == 1) v = s1[gidx];
                else if (seg == 2) v = s2[gidx];
                else v = s3[gidx];
                *(float4*)&ins[r * INS_STRIDE + f4 * 4] = v;
            }
        }
        __syncthreads();

        const float* in0 = &ins[(rg4 + 0) * INS_STRIDE];
        const float* in1 = &ins[(rg4 + 1) * INS_STRIDE];
        const float* in2 = &ins[(rg4 + 2) * INS_STRIDE];
        const float* in3 = &ins[(rg4 + 3) * INS_STRIDE];

        float acc[4][4];
        float sac[4][4];
        #pragma unroll
        for (int r = 0; r < 4; r++)
            #pragma unroll
            for (int c = 0; c < 4; c++) { acc[r][c] = 0.f; sac[r][c] = 0.f; }

        // kk 0..63: kipf + skip fused (shared activation loads)
        #pragma unroll 2
        for (int kq = 0; kq < 16; kq++) {
            int kk = kq * 4;
            float4 a[4];
            a[0] = *(const float4*)&in0[kk];
            a[1] = *(const float4*)&in1[kk];
            a[2] = *(const float4*)&in2[kk];
            a[3] = *(const float4*)&in3[kk];
            #pragma unroll
            for (int j = 0; j < 4; j++) {
                float4 w  = *(const float4*)&Wk_s[(kk + j) * 64 + cg4];
                float4 ws = *(const float4*)&Ws_s[(kk + j) * 64 + cg4];
                #pragma unroll
                for (int r = 0; r < 4; r++) {
                    float av = ((const float*)&a[r])[j];
                    acc[r][0] += av * w.x;  acc[r][1] += av * w.y;
                    acc[r][2] += av * w.z;  acc[r][3] += av * w.w;
                    sac[r][0] += av * ws.x; sac[r][1] += av * ws.y;
                    sac[r][2] += av * ws.z; sac[r][3] += av * ws.w;
                }
            }
        }
        // kk 64..255: kipf only
        #pragma unroll 2
        for (int kq = 16; kq < 64; kq++) {
            int kk = kq * 4;
            float4 a[4];
            a[0] = *(const float4*)&in0[kk];
            a[1] = *(const float4*)&in1[kk];
            a[2] = *(const float4*)&in2[kk];
            a[3] = *(const float4*)&in3[kk];
            #pragma unroll
            for (int j = 0; j < 4; j++) {
                float4 w = *(const float4*)&Wk_s[(kk + j) * 64 + cg4];
                #pragma unroll
                for (int r = 0; r < 4; r++) {
                    float av = ((const float*)&a[r])[j];
                    acc[r][0] += av * w.x; acc[r][1] += av * w.y;
                    acc[r][2] += av * w.z; acc[r][3] += av * w.w;
                }
            }
        }

        float4 bkv = *(const float4*)&bk_s[cg4];
        float4 bsv = *(const float4*)&bs_s[cg4];
        #pragma unroll
        for (int rr = 0; rr < 4; rr++) {
            int row = rowbase + rg4 + rr;
            if (row < NN) {
                float4 o;
                o.x = fmaxf(acc[rr][0] + bkv.x, 0.f) + sac[rr][0] + bsv.x;
                o.y = fmaxf(acc[rr][1] + bkv.y, 0.f) + sac[rr][1] + bsv.y;
                o.z = fmaxf(acc[rr][2] + bkv.z, 0.f) + sac[rr][2] + bsv.z;
                o.w = fmaxf(acc[rr][3] + bkv.w, 0.f) + sac[rr][3] + bsv.w;
                *(float4*)&outp[row * 64 + cg4] = o;
            }
        }
    }
}

// ---------------- mix head GEMM: A = hc@W1, B = hc@W0 + b ------------------
// hc = [H | x] (128 wide). tile 64x64 cols (A cols 0..31, B cols 32..63)
#define MIX_STRIDE 132
#define SMEM_MIX ((8192 + 32 + 64 * MIX_STRIDE) * 4)
__global__ void __launch_bounds__(256, 1) k_mixgemm(
        const float* __restrict__ H, const float* __restrict__ x,
        const float* __restrict__ mw, const float* __restrict__ mb) {
    extern __shared__ float sm[];
    float* Wm_s = sm;            // 8192: [128][64], cols 0..31 = W1, 32..63 = W0
    float* mb_s = sm + 8192;     // 32
    float* ins  = sm + 8224;     // 64 x 132
    const int t = threadIdx.x;

    for (int j = t; j < 8192; j += 256) {
        int f = j >> 6, col = j & 63;
        Wm_s[j] = (col < 32) ? mw[128 * 32 + f * 32 + col] : mw[f * 32 + (col - 32)];
    }
    if (t < 32) mb_s[t] = mb[t];

    const int cg4 = (t & 15) * 4;
    const int rg4 = (t >> 4) * 4;

    for (int tile = blockIdx.x; tile < NT64; tile += gridDim.x) {
        const int rowbase = tile * 64;
        __syncthreads();
        {
            const float4* sH = (const float4*)H;
            const float4* sx = (const float4*)x;
            #pragma unroll
            for (int j = 0; j < 8; j++) {
                int idx = t + j * 256;            // 2048 float4 slots
                int r = idx >> 5, f4 = idx & 31;
                int row = min(rowbase + r, NN - 1);
                int cf = f4 & 15;
                int gidx = row * 16 + cf;
                float4 v = (f4 < 16) ? sH[gidx] : sx[gidx];
                *(float4*)&ins[r * MIX_STRIDE + f4 * 4] = v;
            }
        }
        __syncthreads();

        const float* in0 = &ins[(rg4 + 0) * MIX_STRIDE];
        const float* in1 = &ins[(rg4 + 1) * MIX_STRIDE];
        const float* in2 = &ins[(rg4 + 2) * MIX_STRIDE];
        const float* in3 = &ins[(rg4 + 3) * MIX_STRIDE];

        float acc[4][4];
        #pragma unroll
        for (int r = 0; r < 4; r++)
            #pragma unroll
            for (int c = 0; c < 4; c++) acc[r][c] = 0.f;

        #pragma unroll 2
        for (int kq = 0; kq < 32; kq++) {
            int kk = kq * 4;
            float4 a[4];
            a[0] = *(const float4*)&in0[kk];
            a[1] = *(const float4*)&in1[kk];
            a[2] = *(const float4*)&in2[kk];
            a[3] = *(const float4*)&in3[kk];
            #pragma unroll
            for (int j = 0; j < 4; j++) {
                float4 w = *(const float4*)&Wm_s[(kk + j) * 64 + cg4];
                #pragma unroll
                for (int r = 0; r < 4; r++) {
                    float av = ((const float*)&a[r])[j];
                    acc[r][0] += av * w.x; acc[r][1] += av * w.y;
                    acc[r][2] += av * w.z; acc[r][3] += av * w.w;
                }
            }
        }

        #pragma unroll
        for (int rr = 0; rr < 4; rr++) {
            int row = rowbase + rg4 + rr;
            if (row < NN) {
                if (cg4 < 32) {
                    float4 o = make_float4(acc[rr][0], acc[rr][1], acc[rr][2], acc[rr][3]);
                    *(float4*)&g_A[row * 32 + cg4] = o;
                } else {
                    int cb = cg4 - 32;
                    float4 bv = *(const float4*)&mb_s[cb];
                    float4 o = make_float4(acc[rr][0] + bv.x, acc[rr][1] + bv.y,
                                           acc[rr][2] + bv.z, acc[rr][3] + bv.w);
                    *(float4*)&g_B[row * 32 + cb] = o;
                }
            }
        }
    }
}

// ---------------- final: out = B + L(A) (width 32) -------------------------
__global__ void k_mixlmv(float* __restrict__ outp) {
    int gt = blockIdx.x * blockDim.x + threadIdx.x;
    int node = gt >> 5;
    if (node >= NN) return;
    int lane = gt & 31;
    int beg = g_rp[node], end = g_rp[node + 1];
    float a0 = 0.f, a1 = 0.f, a2 = 0.f, a3 = 0.f;
    int e = beg;
    for (; e + 4 <= end; e += 4) {
        float2 p0 = g_wc[e], p1 = g_wc[e+1], p2 = g_wc[e+2], p3 = g_wc[e+3];
        a0 += p0.x * g_A[__float_as_int(p0.y) * 32 + lane];
        a1 += p1.x * g_A[__float_as_int(p1.y) * 32 + lane];
        a2 += p2.x * g_A[__float_as_int(p2.y) * 32 + lane];
        a3 += p3.x * g_A[__float_as_int(p3.y) * 32 + lane];
    }
    for (; e < end; e++) {
        float2 p = g_wc[e];
        a0 += p.x * g_A[__float_as_int(p.y) * 32 + lane];
    }
    outp[node * 32 + lane] = g_B[node * 32 + lane] + (a0 + a1) + (a2 + a3);
}

// ---------------- launch ---------------------------------------------------
extern "C" void kernel_launch(void* const* d_in, const int* in_sizes, int n_in,
                              void* d_out, int out_size) {
    const float* x  = (const float*)d_in[0];
    const int*   ei = (const int*)d_in[1];
    const float* kw = (const float*)d_in[2];   // [3][4][64][64]
    const float* kb = (const float*)d_in[3];   // [3][64]
    const float* sw = (const float*)d_in[4];   // [3][64][64]
    const float* sb = (const float*)d_in[5];   // [3][64]
    const float* mw = (const float*)d_in[6];   // [2][128][32]
    const float* mb = (const float*)d_in[7];   // [32]
    float* outp = (float*)d_out;
    const int* src = ei;
    const int* dst = ei + NE;

    float *T1, *T2, *T3, *Ha, *Hb;
    cudaGetSymbolAddress((void**)&T1, g_T1);
    cudaGetSymbolAddress((void**)&T2, g_T2);
    cudaGetSymbolAddress((void**)&T3, g_T3);
    cudaGetSymbolAddress((void**)&Ha, g_Ha);
    cudaGetSymbolAddress((void**)&Hb, g_Hb);

    cudaFuncSetAttribute(k_layer, cudaFuncAttributeMaxDynamicSharedMemorySize, SMEM_LAYER);
    cudaFuncSetAttribute(k_mixgemm, cudaFuncAttributeMaxDynamicSharedMemorySize, SMEM_MIX);

    const int gE = (NE + 255) / 256;       // 4688
    const int gN = NB;                     // 391
    const int gW = (NN * 32 + 255) / 256;  // 12500 (warp per node)
    const int gG = 148;                    // persistent GEMM grid

    // graph setup: degrees, dinv, CSR by dst
    k_zero3<<<gN, 256>>>();
    k_degcnt<<<gE, 256>>>(src, dst);
    k_dinv<<<gN, 256>>>();
    k_scan1<<<gN, 256>>>();
    k_scan2<<<1, 512>>>();
    k_scan3<<<gN, 256>>>();
    k_scatter<<<gE, 256>>>(src, dst);

    // layer 0: input = x, output = Hb
    k_lmv64<<<gW, 256>>>(x, nullptr, T1, 1.f, 0.f);
    k_lmv64<<<gW, 256>>>(T1, x, T2, 2.f, -1.f);
    k_lmv64<<<gW, 256>>>(T2, T1, T3, 2.f, -1.f);
    k_layer<<<gG, 256, SMEM_LAYER>>>(x, kw, kb, sw, sb, Hb);

    // layer 1: Hb -> Ha
    k_lmv64<<<gW, 256>>>(Hb, nullptr, T1, 1.f, 0.f);
    k_lmv64<<<gW, 256>>>(T1, Hb, T2, 2.f, -1.f);
    k_lmv64<<<gW, 256>>>(T2, T1, T3, 2.f, -1.f);
    k_layer<<<gG, 256, SMEM_LAYER>>>(Hb, kw + 4 * 64 * 64, kb + 64, sw + 64 * 64, sb + 64, Ha);

    // layer 2: Ha -> Hb
    k_lmv64<<<gW, 256>>>(Ha, nullptr, T1, 1.f, 0.f);
    k_lmv64<<<gW, 256>>>(T1, Ha, T2, 2.f, -1.f);
    k_lmv64<<<gW, 256>>>(T2, T1, T3, 2.f, -1.f);
    k_layer<<<gG, 256, SMEM_LAYER>>>(Ha, kw + 8 * 64 * 64, kb + 128, sw + 2 * 64 * 64, sb + 128, Hb);

    // mix head: A = [Hb|x]@W1, B = [Hb|x]@W0 + b; out = B + L(A)
    k_mixgemm<<<gG, 256, SMEM_MIX>>>(Hb, x, mw, mb);
    k_mixlmv<<<gW, 256>>>(outp);
}

// round 7
// speedup vs baseline: 1.6377x; 1.2075x over previous
#include <cuda_runtime.h>

#define NN 100000
#define NE 1200000
#define NB ((NN + 255) / 256)        // 391 scan blocks
#define NTILES (NN/32)               // 3125 (32-row GEMM tiles)

// ---------------- scratch (static device memory) ---------------------------
__device__ int   g_deg[NN];
__device__ int   g_cnt[NN];
__device__ int   g_fill[NN];
__device__ int   g_rp[NN + 1];
__device__ int   g_bsum[NB + 1];
__device__ int   g_col[NE];
__device__ float g_w[NE];
__device__ float g_dinv[NN];
__device__ float g_T1[NN * 64];
__device__ float g_T2[NN * 64];
__device__ float g_T3[NN * 64];
__device__ float g_Ha[NN * 64];
__device__ float g_Hb[NN * 64];
__device__ float g_A[NN * 32];
__device__ float g_B[NN * 32];

// ---------------- setup kernels --------------------------------------------
__global__ void k_zero3() {
    int i = blockIdx.x * blockDim.x + threadIdx.x;
    if (i < NN) { g_deg[i] = 0; g_cnt[i] = 0; g_fill[i] = 0; }
}

__global__ void k_degcnt(const int* __restrict__ src, const int* __restrict__ dst) {
    int i = blockIdx.x * blockDim.x + threadIdx.x;
    if (i < NE) {
        atomicAdd(&g_deg[src[i]], 1);
        atomicAdd(&g_cnt[dst[i]], 1);
    }
}

__global__ void k_dinv() {
    int i = blockIdx.x * blockDim.x + threadIdx.x;
    if (i < NN) {
        int d = g_deg[i];
        g_dinv[i] = (d > 0) ? rsqrtf((float)d) : 0.0f;
    }
}

// phase 1: per-block sums of g_cnt
__global__ void k_scan1() {
    __shared__ int s[8];
    const int t = threadIdx.x;
    int i = blockIdx.x * 256 + t;
    int v = (i < NN) ? g_cnt[i] : 0;
    #pragma unroll
    for (int d = 16; d; d >>= 1) v += __shfl_down_sync(0xffffffffu, v, d);
    if ((t & 31) == 0) s[t >> 5] = v;
    __syncthreads();
    if (t < 8) {
        int x = s[t];
        #pragma unroll
        for (int d = 4; d; d >>= 1) x += __shfl_down_sync(0xffu, x, d);
        if (t == 0) g_bsum[blockIdx.x] = x;
    }
}

// phase 2: exclusive scan of NB block sums (1 block, 512 threads)
__global__ void k_scan2() {
    __shared__ int wsum[16];
    const int t = threadIdx.x;
    int v = (t < NB) ? g_bsum[t] : 0;
    int xv = v;
    #pragma unroll
    for (int d = 1; d < 32; d <<= 1) {
        int y = __shfl_up_sync(0xffffffffu, xv, d);
        if ((t & 31) >= d) xv += y;
    }
    if ((t & 31) == 31) wsum[t >> 5] = xv;
    __syncthreads();
    if (t < 16) {
        int wv = wsum[t];
        int yv = wv;
        #pragma unroll
        for (int d = 1; d < 16; d <<= 1) {
            int z = __shfl_up_sync(0xffffu, yv, d);
            if (t >= d) yv += z;
        }
        wsum[t] = yv - wv;
    }
    __syncthreads();
    int incl = xv + wsum[t >> 5];
    int excl = incl - v;
    if (t < NB) g_bsum[t] = excl;
    if (t == NB - 1) g_rp[NN] = incl;
}

// phase 3: per-block exclusive scan + block offset
__global__ void k_scan3() {
    __shared__ int wsum[8];
    const int t = threadIdx.x;
    int i = blockIdx.x * 256 + t;
    int v = (i < NN) ? g_cnt[i] : 0;
    int xv = v;
    #pragma unroll
    for (int d = 1; d < 32; d <<= 1) {
        int y = __shfl_up_sync(0xffffffffu, xv, d);
        if ((t & 31) >= d) xv += y;
    }
    if ((t & 31) == 31) wsum[t >> 5] = xv;
    __syncthreads();
    if (t < 8) {
        int wv = wsum[t];
        int yv = wv;
        #pragma unroll
        for (int d = 1; d < 8; d <<= 1) {
            int z = __shfl_up_sync(0xffu, yv, d);
            if (t >= d) yv += z;
        }
        wsum[t] = yv - wv;
    }
    __syncthreads();
    if (i < NN) g_rp[i] = xv - v + wsum[t >> 5] + g_bsum[blockIdx.x];
}

__global__ void k_scatter(const int* __restrict__ src, const int* __restrict__ dst) {
    int i = blockIdx.x * blockDim.x + threadIdx.x;
    if (i < NE) {
        int s = src[i], d = dst[i];
        int pos = g_rp[d] + atomicAdd(&g_fill[d], 1);
        g_col[pos] = s;
        g_w[pos] = -g_dinv[s] * g_dinv[d];
    }
}

// ---------------- sparse matvec: out = alpha * (L z) + beta * sub ----------
__global__ void k_lmv64(const float* __restrict__ z, const float* __restrict__ sub,
                        float* __restrict__ outp, float alpha, float beta) {
    int gt = blockIdx.x * blockDim.x + threadIdx.x;
    int node = gt >> 5;
    if (node >= NN) return;
    int lane = gt & 31;
    int beg = g_rp[node], end = g_rp[node + 1];
    const float2* z2 = (const float2*)z;
    float2 acc = make_float2(0.f, 0.f);
    for (int e = beg; e < end; e++) {
        int s = g_col[e];
        float we = g_w[e];
        float2 v = z2[s * 32 + lane];
        acc.x += we * v.x;
        acc.y += we * v.y;
    }
    float2 r;
    if (sub) {
        float2 sv = ((const float2*)sub)[node * 32 + lane];
        r.x = alpha * acc.x + beta * sv.x;
        r.y = alpha * acc.y + beta * sv.y;
    } else {
        r.x = alpha * acc.x;
        r.y = alpha * acc.y;
    }
    ((float2*)outp)[node * 32 + lane] = r;
}

// ---------------- fused layer GEMM -----------------------------------------
// out = relu([T0|T1|T2|T3] @ Wk + bk) + T0 @ Ws + bs
// smem: Wk 16384f, Ws 4096f, ins 32x256f, bk 64f, bs 64f  -> 115712 B
// 2 blocks/SM: 2 x 115712 = 231424 <= 233472 B per SM
#define SMEM_LAYER (28928 * 4)
__global__ void __launch_bounds__(256, 2) k_layer(
        const float* __restrict__ T0,
        const float* __restrict__ Wk, const float* __restrict__ bk,
        const float* __restrict__ Ws, const float* __restrict__ bs,
        float* __restrict__ outp) {
    extern __shared__ float sm[];
    float* Wk_s = sm;            // 16384
    float* Ws_s = sm + 16384;    // 4096
    float* ins  = sm + 20480;    // 8192  [32 rows][256]
    float* bk_s = sm + 28672;    // 64
    float* bs_s = sm + 28736;    // 64
    const int t = threadIdx.x;   // 256 threads

    for (int j = t; j < 4096; j += 256) ((float4*)Wk_s)[j] = ((const float4*)Wk)[j];
    for (int j = t; j < 1024; j += 256) ((float4*)Ws_s)[j] = ((const float4*)Ws)[j];
    if (t < 64) { bk_s[t] = bk[t]; bs_s[t] = bs[t]; }

    const int cg = (t & 15) * 4;   // output col base (4 cols)
    const int r0 = (t >> 4) * 2;   // row base (2 rows)

    for (int tile = blockIdx.x; tile < NTILES; tile += gridDim.x) {
        const int rowbase = tile * 32;
        __syncthreads();
        {
            const float4* s0 = (const float4*)T0;
            const float4* s1 = (const float4*)g_T1;
            const float4* s2 = (const float4*)g_T2;
            const float4* s3 = (const float4*)g_T3;
            #pragma unroll
            for (int j = 0; j < 2; j++) {
                int i = t + j * 256;
                int r = i >> 4, f4 = i & 15;
                int gidx = (rowbase + r) * 16 + f4;
                *(float4*)&ins[r * 256 +   0 + f4 * 4] = s0[gidx];
                *(float4*)&ins[r * 256 +  64 + f4 * 4] = s1[gidx];
                *(float4*)&ins[r * 256 + 128 + f4 * 4] = s2[gidx];
                *(float4*)&ins[r * 256 + 192 + f4 * 4] = s3[gidx];
            }
        }
        __syncthreads();

        const float* in0 = &ins[r0 * 256];
        const float* in1 = in0 + 256;
        float4 acc0 = make_float4(0, 0, 0, 0), acc1 = acc0;
        #pragma unroll 8
        for (int kk = 0; kk < 256; kk++) {
            float4 wv = *(const float4*)&Wk_s[kk * 64 + cg];
            float a0 = in0[kk], a1 = in1[kk];
            acc0.x += a0 * wv.x; acc0.y += a0 * wv.y; acc0.z += a0 * wv.z; acc0.w += a0 * wv.w;
            acc1.x += a1 * wv.x; acc1.y += a1 * wv.y; acc1.z += a1 * wv.z; acc1.w += a1 * wv.w;
        }
        float4 sk0 = make_float4(0, 0, 0, 0), sk1 = sk0;
        #pragma unroll 8
        for (int kk = 0; kk < 64; kk++) {
            float4 wv = *(const float4*)&Ws_s[kk * 64 + cg];
            float a0 = in0[kk], a1 = in1[kk];
            sk0.x += a0 * wv.x; sk0.y += a0 * wv.y; sk0.z += a0 * wv.z; sk0.w += a0 * wv.w;
            sk1.x += a1 * wv.x; sk1.y += a1 * wv.y; sk1.z += a1 * wv.z; sk1.w += a1 * wv.w;
        }
        float4 bkv = *(const float4*)&bk_s[cg];
        float4 bsv = *(const float4*)&bs_s[cg];
        float4 o0, o1;
        o0.x = fmaxf(acc0.x + bkv.x, 0.f) + sk0.x + bsv.x;
        o0.y = fmaxf(acc0.y + bkv.y, 0.f) + sk0.y + bsv.y;
        o0.z = fmaxf(acc0.z + bkv.z, 0.f) + sk0.z + bsv.z;
        o0.w = fmaxf(acc0.w + bkv.w, 0.f) + sk0.w + bsv.w;
        o1.x = fmaxf(acc1.x + bkv.x, 0.f) + sk1.x + bsv.x;
        o1.y = fmaxf(acc1.y + bkv.y, 0.f) + sk1.y + bsv.y;
        o1.z = fmaxf(acc1.z + bkv.z, 0.f) + sk1.z + bsv.z;
        o1.w = fmaxf(acc1.w + bkv.w, 0.f) + sk1.w + bsv.w;
        *(float4*)&outp[(rowbase + r0) * 64 + cg]     = o0;
        *(float4*)&outp[(rowbase + r0 + 1) * 64 + cg] = o1;
    }
}

// ---------------- mix head GEMM: A = hc@W1, B = hc@W0 + b ------------------
// hc = [H | x] (128 wide). smem: Wm 8192f, ins 32x128f, mb 32f -> 49280 B
#define SMEM_MIX (12320 * 4)
__global__ void __launch_bounds__(256, 4) k_mixgemm(
        const float* __restrict__ H, const float* __restrict__ x,
        const float* __restrict__ mw, const float* __restrict__ mb) {
    extern __shared__ float sm[];
    float* Wm_s = sm;           // 8192  [128][64]: cols 0..31 = W1, 32..63 = W0
    float* ins  = sm + 8192;    // 4096  [32 rows][128]
    float* mb_s = sm + 12288;   // 32
    const int t = threadIdx.x;

    for (int j = t; j < 8192; j += 256) {
        int f = j >> 6, col = j & 63;
        Wm_s[j] = (col < 32) ? mw[128 * 32 + f * 32 + col] : mw[f * 32 + (col - 32)];
    }
    if (t < 32) mb_s[t] = mb[t];

    const int cg = (t & 15) * 4;
    const int r0 = (t >> 4) * 2;

    for (int tile = blockIdx.x; tile < NTILES; tile += gridDim.x) {
        const int rowbase = tile * 32;
        __syncthreads();
        {
            const float4* sH = (const float4*)H;
            const float4* sx = (const float4*)x;
            #pragma unroll
            for (int j = 0; j < 2; j++) {
                int i = t + j * 256;
                int r = i >> 4, f4 = i & 15;
                int gidx = (rowbase + r) * 16 + f4;
                *(float4*)&ins[r * 128 +      f4 * 4] = sH[gidx];
                *(float4*)&ins[r * 128 + 64 + f4 * 4] = sx[gidx];
            }
        }
        __syncthreads();

        const float* in0 = &ins[r0 * 128];
        const float* in1 = in0 + 128;
        float4 acc0 = make_float4(0, 0, 0, 0), acc1 = acc0;
        #pragma unroll 8
        for (int kk = 0; kk < 128; kk++) {
            float4 wv = *(const float4*)&Wm_s[kk * 64 + cg];
            float a0 = in0[kk], a1 = in1[kk];
            acc0.x += a0 * wv.x; acc0.y += a0 * wv.y; acc0.z += a0 * wv.z; acc0.w += a0 * wv.w;
            acc1.x += a1 * wv.x; acc1.y += a1 * wv.y; acc1.z += a1 * wv.z; acc1.w += a1 * wv.w;
        }
        if (cg < 32) {
            *(float4*)&g_A[(rowbase + r0) * 32 + cg]     = acc0;
            *(float4*)&g_A[(rowbase + r0 + 1) * 32 + cg] = acc1;
        } else {
            float4 bv = *(const float4*)&mb_s[cg - 32];
            acc0.x += bv.x; acc0.y += bv.y; acc0.z += bv.z; acc0.w += bv.w;
            acc1.x += bv.x; acc1.y += bv.y; acc1.z += bv.z; acc1.w += bv.w;
            *(float4*)&g_B[(rowbase + r0) * 32 + cg - 32]     = acc0;
            *(float4*)&g_B[(rowbase + r0 + 1) * 32 + cg - 32] = acc1;
        }
    }
}

// ---------------- final: out = B + L(A) (width 32) -------------------------
__global__ void k_mixlmv(float* __restrict__ outp) {
    int gt = blockIdx.x * blockDim.x + threadIdx.x;
    int node = gt >> 5;
    if (node >= NN) return;
    int lane = gt & 31;
    int beg = g_rp[node], end = g_rp[node + 1];
    float acc = 0.f;
    for (int e = beg; e < end; e++) {
        acc += g_w[e] * g_A[g_col[e] * 32 + lane];
    }
    outp[node * 32 + lane] = g_B[node * 32 + lane] + acc;
}

// ---------------- launch ---------------------------------------------------
extern "C" void kernel_launch(void* const* d_in, const int* in_sizes, int n_in,
                              void* d_out, int out_size) {
    const float* x  = (const float*)d_in[0];
    const int*   ei = (const int*)d_in[1];
    const float* kw = (const float*)d_in[2];   // [3][4][64][64]
    const float* kb = (const float*)d_in[3];   // [3][64]
    const float* sw = (const float*)d_in[4];   // [3][64][64]
    const float* sb = (const float*)d_in[5];   // [3][64]
    const float* mw = (const float*)d_in[6];   // [2][128][32]
    const float* mb = (const float*)d_in[7];   // [32]
    float* outp = (float*)d_out;
    const int* src = ei;
    const int* dst = ei + NE;

    float *T1, *T2, *T3, *Ha, *Hb;
    cudaGetSymbolAddress((void**)&T1, g_T1);
    cudaGetSymbolAddress((void**)&T2, g_T2);
    cudaGetSymbolAddress((void**)&T3, g_T3);
    cudaGetSymbolAddress((void**)&Ha, g_Ha);
    cudaGetSymbolAddress((void**)&Hb, g_Hb);

    cudaFuncSetAttribute(k_layer, cudaFuncAttributeMaxDynamicSharedMemorySize, SMEM_LAYER);
    cudaFuncSetAttribute(k_mixgemm, cudaFuncAttributeMaxDynamicSharedMemorySize, SMEM_MIX);

    const int gE = (NE + 255) / 256;       // 4688
    const int gN = NB;                     // 391
    const int gW = (NN * 32 + 255) / 256;  // 12500 (warp per node)
    const int gG = 296;                    // k_layer: 2 blocks/SM target
    const int gM = 592;                    // mixgemm grid

    // graph setup: degrees, dinv, CSR by dst
    k_zero3<<<gN, 256>>>();
    k_degcnt<<<gE, 256>>>(src, dst);
    k_dinv<<<gN, 256>>>();
    k_scan1<<<gN, 256>>>();
    k_scan2<<<1, 512>>>();
    k_scan3<<<gN, 256>>>();
    k_scatter<<<gE, 256>>>(src, dst);

    // layer 0: input = x, output = Hb
    k_lmv64<<<gW, 256>>>(x, nullptr, T1, 1.f, 0.f);
    k_lmv64<<<gW, 256>>>(T1, x, T2, 2.f, -1.f);
    k_lmv64<<<gW, 256>>>(T2, T1, T3, 2.f, -1.f);
    k_layer<<<gG, 256, SMEM_LAYER>>>(x, kw, kb, sw, sb, Hb);

    // layer 1: Hb -> Ha
    k_lmv64<<<gW, 256>>>(Hb, nullptr, T1, 1.f, 0.f);
    k_lmv64<<<gW, 256>>>(T1, Hb, T2, 2.f, -1.f);
    k_lmv64<<<gW, 256>>>(T2, T1, T3, 2.f, -1.f);
    k_layer<<<gG, 256, SMEM_LAYER>>>(Hb, kw + 4 * 64 * 64, kb + 64, sw + 64 * 64, sb + 64, Ha);

    // layer 2: Ha -> Hb
    k_lmv64<<<gW, 256>>>(Ha, nullptr, T1, 1.f, 0.f);
    k_lmv64<<<gW, 256>>>(T1, Ha, T2, 2.f, -1.f);
    k_lmv64<<<gW, 256>>>(T2, T1, T3, 2.f, -1.f);
    k_layer<<<gG, 256, SMEM_LAYER>>>(Ha, kw + 8 * 64 * 64, kb + 128, sw + 2 * 64 * 64, sb + 128, Hb);

    // mix head: A = [Hb|x]@W1, B = [Hb|x]@W0 + b; out = B + L(A)
    k_mixgemm<<<gM, 256, SMEM_MIX>>>(Hb, x, mw, mb);
    k_mixlmv<<<gW, 256>>>(outp);
}